// round 2
// baseline (speedup 1.0000x reference)
#include <cuda_runtime.h>

#define NTYPES 20
#define LMAXC  13
#define DV     64
#define NRES_MAX 2048
#define B_MAX    16

__constant__ int c_res_len[NTYPES] = {3,4,5,5,6,6,6,7,7,7,7,7,8,8,8,9,10,10,11,13};

__device__ int   g_starts[NRES_MAX];
__device__ int   g_rowmap[NRES_MAX * (LMAXC + 1)];
__device__ int   g_totrows;
__device__ float g_dif[B_MAX * NRES_MAX * (LMAXC + 1) * 4];   // (b, i, l, 4) padded, 7.3 MB

// ---------------------------------------------------------------------------
// Setup: scan lengths -> starts; scan (L+1) -> row starts; fill rowmap.
// ---------------------------------------------------------------------------
__global__ void setup_kernel(const int* __restrict__ seq, int nres) {
    __shared__ int sa[NRES_MAX];
    __shared__ int sb[NRES_MAX];
    const int tid = threadIdx.x;

    // pass 1: atom starts
    for (int j = tid; j < nres; j += blockDim.x) sa[j] = c_res_len[seq[j]];
    __syncthreads();
    int* a = sa; int* b = sb;
    for (int off = 1; off < nres; off <<= 1) {
        for (int j = tid; j < nres; j += blockDim.x)
            b[j] = a[j] + ((j >= off) ? a[j - off] : 0);
        __syncthreads();
        int* t = a; a = b; b = t;
    }
    for (int j = tid; j < nres; j += blockDim.x)
        g_starts[j] = (j == 0) ? 0 : a[j - 1];
    __syncthreads();

    // pass 2: row starts over (L+1)
    for (int j = tid; j < nres; j += blockDim.x) sa[j] = c_res_len[seq[j]] + 1;
    __syncthreads();
    a = sa; b = sb;
    for (int off = 1; off < nres; off <<= 1) {
        for (int j = tid; j < nres; j += blockDim.x)
            b[j] = a[j] + ((j >= off) ? a[j - off] : 0);
        __syncthreads();
        int* t = a; a = b; b = t;
    }
    for (int j = tid; j < nres; j += blockDim.x) {
        const int L  = c_res_len[seq[j]];
        const int rs = a[j] - (L + 1);
        for (int m = 0; m <= L; ++m) g_rowmap[rs + m] = (j << 4) | m;
    }
    if (tid == 0) g_totrows = a[nres - 1];
}

// ---------------------------------------------------------------------------
// Diff precompute: g_dif[b][i][l][0..3] = (pos_atm - pos_amn) padded with 0.
// ---------------------------------------------------------------------------
__global__ void diff_kernel(const float* __restrict__ pa, const float* __restrict__ pn,
                            const int* __restrict__ seq, int B, int nres, int atoms) {
    const int idx = blockIdx.x * 256 + threadIdx.x;
    const int per_b = nres * (LMAXC + 1) * 4;
    if (idx >= B * per_b) return;
    const int b = idx / per_b;
    const int r = idx - b * per_b;
    const int i = r / 56;
    const int j = r - i * 56;
    const int l = j >> 2, d = j & 3;
    const int L = c_res_len[seq[i]];
    float val = 0.0f;
    if (l < L && d < 3) {
        const int s = g_starts[i];
        val = pa[((size_t)b * atoms + s + l) * 3 + d] -
              pn[((size_t)b * nres + i) * 3 + d];
    }
    g_dif[idx] = val;
}

// ---------------------------------------------------------------------------
// Main: one pair (row m, channel v) per thread, weights in registers,
// diffs staged in tiny double-buffered smem, loop over batches.
// ---------------------------------------------------------------------------
#define PACK_DUP(dst, w) \
    asm("mov.b64 %0, {%1, %2};" : "=l"(dst) : "r"(__float_as_uint(w)), "r"(__float_as_uint(w)))
#define FMA2(acc, x, y) \
    asm("fma.rn.f32x2 %0, %1, %2, %3;" : "=l"(acc) : "l"(x), "l"(y), "l"(acc))
#define UNPACK2(lo, hi, src) \
    asm("mov.b64 {%0, %1}, %2;" : "=r"(lo), "=r"(hi) : "l"(src))
#define LDS_V2U64(x, y, addr) \
    asm volatile("ld.shared.v2.u64 {%0, %1}, [%2];" : "=l"(x), "=l"(y) : "r"(addr))

__device__ __forceinline__ unsigned smem_u32(const void* p) {
    unsigned r;
    asm("{ .reg .u64 t; cvta.to.shared.u64 t, %1; cvt.u32.u64 %0, t; }" : "=r"(r) : "l"(p));
    return r;
}

template <int L>
__device__ __forceinline__ void batch_loop(
    int tid, int B, bool active, unsigned sbase, int slot,
    const float* __restrict__ wr, float* op, long ostride,
    const float* gdp, long gstride, float* sdif_flat)
{
    // load + pack weight row once
    unsigned long long ww[L];
#pragma unroll
    for (int l = 0; l < L; ++l) {
        const float w = __ldg(wr + l);
        PACK_DUP(ww[l], w);
    }

    const unsigned myrow = sbase + slot * 56 * 4;   // this thread's slot, buffer 0

#pragma unroll 1
    for (int b = 0; b < B; ++b) {
        // stage next batch into the other buffer
        if (b + 1 < B && tid < 224)
            sdif_flat[((b + 1) & 1) * 224 + tid] = gdp[(long)(b + 1) * gstride];

        const unsigned cur = myrow + (b & 1) * 224 * 4;
        unsigned long long a01 = 0ull, a2p = 0ull;
#pragma unroll
        for (int l = 0; l < L; ++l) {
            unsigned long long d01, d2p;
            LDS_V2U64(d01, d2p, cur + l * 16);
            FMA2(a01, ww[l], d01);
            FMA2(a2p, ww[l], d2p);
        }
        if (active) {
            unsigned lo, hi, lo2, hi2;
            UNPACK2(lo, hi, a01);
            UNPACK2(lo2, hi2, a2p);
            op[0] = __uint_as_float(lo);
            op[1] = __uint_as_float(hi);
            op[2] = __uint_as_float(lo2);
        }
        op += ostride;
        __syncthreads();
    }
}

__global__ __launch_bounds__(256) void posmix_kernel(
    const float* __restrict__ W_amn, const float* __restrict__ W_atm,
    const int* __restrict__ seq,
    int B, int nres, int atoms, float* __restrict__ out)
{
    const int totrows = g_totrows;
    const int row0 = blockIdx.x * 4;
    if (row0 >= totrows) return;

    __shared__ float sdif[2 * 4 * 56];   // 2 buffers x 4 slots x 14 float4
    __shared__ int   si[4];

    const int tid  = threadIdx.x;
    const int slot = tid >> 6;
    const int v    = tid & 63;
    const int row  = row0 + slot;
    const bool active = (row < totrows);
    const int rowc = active ? row : (totrows - 1);

    const int rm = g_rowmap[rowc];
    const int i  = rm >> 4;
    const int m  = rm & 15;
    const int t  = seq[i];
    const int L  = c_res_len[t];
    const bool is_amn = (m == L);

    const float* wr = is_amn
        ? (W_amn + ((size_t)t * DV + v) * LMAXC)
        : (W_atm + (((size_t)t * LMAXC + m) * DV + v) * LMAXC);

    const int start = g_starts[i];
    size_t base; long ostride;
    if (is_amn) {
        base    = (size_t)B * atoms * (DV * 3) + ((size_t)i * DV + v) * 3;
        ostride = (long)nres * (DV * 3);
    } else {
        base    = ((size_t)(start + m) * DV + v) * 3;
        ostride = (long)atoms * (DV * 3);
    }
    float* op = out + base;

    if (v == 0) si[slot] = i;
    __syncthreads();

    // staging mapping (threads 0..223)
    const int sslot = tid / 56;
    const int sj    = tid - sslot * 56;
    const long gstride = (long)nres * 56;
    const float* gdp = g_dif;
    if (tid < 224) {
        gdp = g_dif + (size_t)si[sslot] * 56 + sj;
        sdif[tid] = gdp[0];                 // batch 0, buffer 0
    }
    __syncthreads();

    const unsigned sbase = smem_u32(sdif);

    switch (L) {
        case  3: batch_loop< 3>(tid, B, active, sbase, slot, wr, op, ostride, gdp, gstride, sdif); break;
        case  4: batch_loop< 4>(tid, B, active, sbase, slot, wr, op, ostride, gdp, gstride, sdif); break;
        case  5: batch_loop< 5>(tid, B, active, sbase, slot, wr, op, ostride, gdp, gstride, sdif); break;
        case  6: batch_loop< 6>(tid, B, active, sbase, slot, wr, op, ostride, gdp, gstride, sdif); break;
        case  7: batch_loop< 7>(tid, B, active, sbase, slot, wr, op, ostride, gdp, gstride, sdif); break;
        case  8: batch_loop< 8>(tid, B, active, sbase, slot, wr, op, ostride, gdp, gstride, sdif); break;
        case  9: batch_loop< 9>(tid, B, active, sbase, slot, wr, op, ostride, gdp, gstride, sdif); break;
        case 10: batch_loop<10>(tid, B, active, sbase, slot, wr, op, ostride, gdp, gstride, sdif); break;
        case 11: batch_loop<11>(tid, B, active, sbase, slot, wr, op, ostride, gdp, gstride, sdif); break;
        default: batch_loop<13>(tid, B, active, sbase, slot, wr, op, ostride, gdp, gstride, sdif); break;
    }
}

// ---------------------------------------------------------------------------
extern "C" void kernel_launch(void* const* d_in, const int* in_sizes, int n_in,
                              void* d_out, int out_size) {
    const float* pos_atm = (const float*)d_in[0];
    const float* pos_amn = (const float*)d_in[1];
    const float* W_amn   = (const float*)d_in[2];
    const float* W_atm   = (const float*)d_in[3];
    const int*   seq     = (const int*)d_in[4];

    const int nres  = in_sizes[4];
    const int B     = in_sizes[1] / (nres * 3);
    const int atoms = in_sizes[0] / (B * 3);

    setup_kernel<<<1, 1024>>>(seq, nres);
    const int ndiff = B * nres * (LMAXC + 1) * 4;
    diff_kernel<<<(ndiff + 255) / 256, 256>>>(pos_atm, pos_amn, seq, B, nres, atoms);
    const int nblocks = (nres * (LMAXC + 1) + 3) / 4;
    posmix_kernel<<<nblocks, 256>>>(W_amn, W_atm, seq, B, nres, atoms, (float*)d_out);
}

// round 4
// speedup vs baseline: 1.2400x; 1.2400x over previous
#include <cuda_runtime.h>

#define NTYPES 20
#define LMAXC  13
#define DV     64
#define NRES_MAX 2048
#define B_MAX    16

__constant__ int c_res_len[NTYPES] = {3,4,5,5,6,6,6,7,7,7,7,7,8,8,8,9,10,10,11,13};

__device__ int   g_starts[NRES_MAX];
__device__ int   g_rowmap[NRES_MAX * (LMAXC + 1)];
__device__ int   g_totrows;
// layout: (i, b, l, 4)  -> i stride = B*56
__device__ float g_dif[NRES_MAX * B_MAX * (LMAXC + 1) * 4];

// ---------------------------------------------------------------------------
// Setup: two warp-shuffle scans (atom starts, row starts) + rowmap fill.
// One block, 1024 threads, each thread owns residues 2*tid and 2*tid+1.
// ---------------------------------------------------------------------------
__device__ __forceinline__ int block_excl_scan_pair(int my, int tid, int* wsum) {
    const int lane = tid & 31, wid = tid >> 5;
    int s = my;
#pragma unroll
    for (int o = 1; o < 32; o <<= 1) {
        int n = __shfl_up_sync(~0u, s, o);
        if (lane >= o) s += n;
    }
    if (lane == 31) wsum[wid] = s;
    __syncthreads();
    if (wid == 0) {
        int t = wsum[lane];
#pragma unroll
        for (int o = 1; o < 32; o <<= 1) {
            int n = __shfl_up_sync(~0u, t, o);
            if (lane >= o) t += n;
        }
        wsum[lane] = t;
    }
    __syncthreads();
    int base = ((wid > 0) ? wsum[wid - 1] : 0) + (s - my);
    __syncthreads();   // wsum reused by next scan
    return base;       // exclusive prefix of this thread's pair
}

__global__ void setup_kernel(const int* __restrict__ seq, int nres) {
    __shared__ int wsum[32];
    const int tid = threadIdx.x;
    const int j0 = 2 * tid, j1 = 2 * tid + 1;
    const int l0 = (j0 < nres) ? c_res_len[seq[j0]] : 0;
    const int l1 = (j1 < nres) ? c_res_len[seq[j1]] : 0;

    // scan 1: atom starts
    int base = block_excl_scan_pair(l0 + l1, tid, wsum);
    if (j0 < nres) g_starts[j0] = base;
    if (j1 < nres) g_starts[j1] = base + l0;

    // scan 2: row starts over (L+1)
    const int r0 = (j0 < nres) ? l0 + 1 : 0;
    const int r1 = (j1 < nres) ? l1 + 1 : 0;
    int rbase = block_excl_scan_pair(r0 + r1, tid, wsum);
    if (j0 < nres)
        for (int m = 0; m < r0; ++m) g_rowmap[rbase + m] = (j0 << 4) | m;
    if (j1 < nres)
        for (int m = 0; m < r1; ++m) g_rowmap[rbase + r0 + m] = (j1 << 4) | m;
    // exactly one thread owns the last residue
    if (j0 == nres - 1 || (j1 == nres - 1))
        g_totrows = rbase + r0 + r1;
}

// ---------------------------------------------------------------------------
// Diff precompute: g_dif[i][b][l][d] = pos_atm - pos_amn (0 padded).
// ---------------------------------------------------------------------------
__global__ void diff_kernel(const float* __restrict__ pa, const float* __restrict__ pn,
                            const int* __restrict__ seq, int B, int nres, int atoms) {
    const int idx = blockIdx.x * 256 + threadIdx.x;
    const int per_i = B * 56;
    if (idx >= nres * per_i) return;
    const int i = idx / per_i;
    const int r = idx - i * per_i;
    const int b = r / 56;
    const int j = r - b * 56;
    const int l = j >> 2, d = j & 3;
    const int L = c_res_len[seq[i]];
    float val = 0.0f;
    if (l < L && d < 3) {
        const int s = g_starts[i];
        val = pa[((size_t)b * atoms + s + l) * 3 + d] -
              pn[((size_t)b * nres + i) * 3 + d];
    }
    g_dif[idx] = val;
}

// ---------------------------------------------------------------------------
// Main: one (row m, channel v) pair per thread. Weights in registers (packed
// f32x2 dup). ALL batches of the block's diffs preloaded into smem once.
// Batch loop: L x LDS.128 + 2L x fma.f32x2 + 3 x STG.  No in-loop syncs.
// ---------------------------------------------------------------------------
#define PACK_DUP(dst, w) \
    asm("mov.b64 %0, {%1, %2};" : "=l"(dst) : "r"(__float_as_uint(w)), "r"(__float_as_uint(w)))
#define FMA2(acc, x, y) \
    asm("fma.rn.f32x2 %0, %1, %2, %3;" : "=l"(acc) : "l"(x), "l"(y), "l"(acc))
#define ADD2(dst, x, y) \
    asm("add.rn.f32x2 %0, %1, %2;" : "=l"(dst) : "l"(x), "l"(y))
#define UNPACK2(lo, hi, src) \
    asm("mov.b64 {%0, %1}, %2;" : "=r"(lo), "=r"(hi) : "l"(src))
#define LDS_V2U64(x, y, addr) \
    asm volatile("ld.shared.v2.u64 {%0, %1}, [%2];" : "=l"(x), "=l"(y) : "r"(addr))

__device__ __forceinline__ unsigned smem_u32(const void* p) {
    unsigned r;
    asm("{ .reg .u64 t; cvta.to.shared.u64 t, %1; cvt.u32.u64 %0, t; }" : "=r"(r) : "l"(p));
    return r;
}

template <int L>
__device__ __forceinline__ void batch_loop(
    int B, bool active, unsigned sbase, int slot,
    const float* __restrict__ wr, float* op, long ostride)
{
    unsigned long long ww[L];
#pragma unroll
    for (int l = 0; l < L; ++l) {
        const float w = __ldg(wr + l);
        PACK_DUP(ww[l], w);
    }

    unsigned cur = sbase + (unsigned)(slot * B) * 224u;

#pragma unroll 2
    for (int b = 0; b < B; ++b) {
        unsigned long long aA = 0ull, aB = 0ull, cA = 0ull, cB = 0ull;
#pragma unroll
        for (int l = 0; l < L; ++l) {
            unsigned long long d01, d2p;
            LDS_V2U64(d01, d2p, cur + l * 16);
            if (l & 1) { FMA2(aB, ww[l], d01); FMA2(cB, ww[l], d2p); }
        else       { FMA2(aA, ww[l], d01); FMA2(cA, ww[l], d2p); }
        }
        unsigned long long a01, a2p;
        ADD2(a01, aA, aB);
        ADD2(a2p, cA, cB);
        if (active) {
            unsigned lo, hi, lo2, hi2;
            UNPACK2(lo, hi, a01);
            UNPACK2(lo2, hi2, a2p);
            op[0] = __uint_as_float(lo);
            op[1] = __uint_as_float(hi);
            op[2] = __uint_as_float(lo2);
        }
        op += ostride;
        cur += 224u;
    }
}

__global__ __launch_bounds__(256) void posmix_kernel(
    const float* __restrict__ W_amn, const float* __restrict__ W_atm,
    const int* __restrict__ seq,
    int B, int nres, int atoms, float* __restrict__ out)
{
    const int totrows = g_totrows;
    const int row0 = blockIdx.x * 4;
    if (row0 >= totrows) return;

    __shared__ float sdif[4 * B_MAX * 56];   // 14336 B
    __shared__ int   si4[4];

    const int tid  = threadIdx.x;
    const int slot = tid >> 6;
    const int v    = tid & 63;
    const int row  = row0 + slot;
    const bool active = (row < totrows);
    const int rowc = active ? row : (totrows - 1);

    const int rm = g_rowmap[rowc];
    const int i  = rm >> 4;
    const int m  = rm & 15;
    const int t  = seq[i];
    const int L  = c_res_len[t];
    const bool is_amn = (m == L);

    const float* wr = is_amn
        ? (W_amn + ((size_t)t * DV + v) * LMAXC)
        : (W_atm + (((size_t)t * LMAXC + m) * DV + v) * LMAXC);

    const int start = g_starts[i];
    size_t base; long ostride;
    if (is_amn) {
        base    = (size_t)B * atoms * (DV * 3) + ((size_t)i * DV + v) * 3;
        ostride = (long)nres * (DV * 3);
    } else {
        base    = ((size_t)(start + m) * DV + v) * 3;
        ostride = (long)atoms * (DV * 3);
    }
    float* op = out + base;

    if (v == 0) si4[slot] = i;
    __syncthreads();

    // preload all B batches of this slot's residue diffs (coalesced float4)
    {
        const float4* src = reinterpret_cast<const float4*>(
            g_dif + (size_t)si4[slot] * (B * 56));
        float4* dst = reinterpret_cast<float4*>(sdif + slot * (B * 56));
        const int n4 = B * 14;     // 224 float4 per slot
        for (int j = v; j < n4; j += 64) dst[j] = src[j];
    }
    __syncthreads();

    const unsigned sbase = smem_u32(sdif);

    switch (L) {
        case  3: batch_loop< 3>(B, active, sbase, slot, wr, op, ostride); break;
        case  4: batch_loop< 4>(B, active, sbase, slot, wr, op, ostride); break;
        case  5: batch_loop< 5>(B, active, sbase, slot, wr, op, ostride); break;
        case  6: batch_loop< 6>(B, active, sbase, slot, wr, op, ostride); break;
        case  7: batch_loop< 7>(B, active, sbase, slot, wr, op, ostride); break;
        case  8: batch_loop< 8>(B, active, sbase, slot, wr, op, ostride); break;
        case  9: batch_loop< 9>(B, active, sbase, slot, wr, op, ostride); break;
        case 10: batch_loop<10>(B, active, sbase, slot, wr, op, ostride); break;
        case 11: batch_loop<11>(B, active, sbase, slot, wr, op, ostride); break;
        default: batch_loop<13>(B, active, sbase, slot, wr, op, ostride); break;
    }
}

// ---------------------------------------------------------------------------
extern "C" void kernel_launch(void* const* d_in, const int* in_sizes, int n_in,
                              void* d_out, int out_size) {
    const float* pos_atm = (const float*)d_in[0];
    const float* pos_amn = (const float*)d_in[1];
    const float* W_amn   = (const float*)d_in[2];
    const float* W_atm   = (const float*)d_in[3];
    const int*   seq     = (const int*)d_in[4];

    const int nres  = in_sizes[4];
    const int B     = in_sizes[1] / (nres * 3);
    const int atoms = in_sizes[0] / (B * 3);

    setup_kernel<<<1, 1024>>>(seq, nres);
    const int ndiff = nres * B * (LMAXC + 1) * 4;
    diff_kernel<<<(ndiff + 255) / 256, 256>>>(pos_atm, pos_amn, seq, B, nres, atoms);
    const int nblocks = (nres * (LMAXC + 1) + 3) / 4;
    posmix_kernel<<<nblocks, 256>>>(W_amn, W_atm, seq, B, nres, atoms, (float*)d_out);
}

// round 5
// speedup vs baseline: 1.3346x; 1.0763x over previous
#include <cuda_runtime.h>

#define NTYPES 20
#define LMAXC  13
#define DV     64
#define NRES_MAX 2048
#define B_MAX    16

__constant__ int c_res_len[NTYPES] = {3,4,5,5,6,6,6,7,7,7,7,7,8,8,8,9,10,10,11,13};

// packed rowmap entry: i (bits 0..10) | m (bits 11..14) | start (bits 15..28)
__device__ int g_rowmap[NRES_MAX * (LMAXC + 1)];
__device__ int g_totrows;

// ---------------------------------------------------------------------------
// Setup: two warp-shuffle scans (atom starts, row starts) + packed rowmap.
// One block, 1024 threads, each thread owns residues 2*tid and 2*tid+1.
// ---------------------------------------------------------------------------
__device__ __forceinline__ int block_excl_scan_pair(int my, int tid, int* wsum) {
    const int lane = tid & 31, wid = tid >> 5;
    int s = my;
#pragma unroll
    for (int o = 1; o < 32; o <<= 1) {
        int n = __shfl_up_sync(~0u, s, o);
        if (lane >= o) s += n;
    }
    if (lane == 31) wsum[wid] = s;
    __syncthreads();
    if (wid == 0) {
        int t = wsum[lane];
#pragma unroll
        for (int o = 1; o < 32; o <<= 1) {
            int n = __shfl_up_sync(~0u, t, o);
            if (lane >= o) t += n;
        }
        wsum[lane] = t;
    }
    __syncthreads();
    int base = ((wid > 0) ? wsum[wid - 1] : 0) + (s - my);
    __syncthreads();   // wsum reused by next scan
    return base;
}

__global__ void setup_kernel(const int* __restrict__ seq, int nres) {
    __shared__ int wsum[32];
    __shared__ int slen[NTYPES];
    const int tid = threadIdx.x;
    if (tid < NTYPES) slen[tid] = c_res_len[tid];
    __syncthreads();

    const int j0 = 2 * tid, j1 = 2 * tid + 1;
    const int l0 = (j0 < nres) ? slen[seq[j0]] : 0;
    const int l1 = (j1 < nres) ? slen[seq[j1]] : 0;

    // scan 1: atom starts
    const int base = block_excl_scan_pair(l0 + l1, tid, wsum);
    const int start0 = base;
    const int start1 = base + l0;

    // scan 2: row starts over (L+1)
    const int r0 = (j0 < nres) ? l0 + 1 : 0;
    const int r1 = (j1 < nres) ? l1 + 1 : 0;
    const int rbase = block_excl_scan_pair(r0 + r1, tid, wsum);

    if (j0 < nres) {
        const int rec = j0 | (start0 << 15);
        for (int m = 0; m < r0; ++m) g_rowmap[rbase + m] = rec | (m << 11);
    }
    if (j1 < nres) {
        const int rec = j1 | (start1 << 15);
        for (int m = 0; m < r1; ++m) g_rowmap[rbase + r0 + m] = rec | (m << 11);
    }
    if (j0 == nres - 1 || j1 == nres - 1)
        g_totrows = rbase + r0 + r1;
}

// ---------------------------------------------------------------------------
// Main: one (row m, channel v) pair per thread. Weights in registers (packed
// f32x2 dup). Diffs computed in-block for all B batches directly into smem.
// Batch loop: L x LDS.128 + 2L x fma.f32x2 + 3 x STG.  No in-loop syncs.
// ---------------------------------------------------------------------------
#define PACK_DUP(dst, w) \
    asm("mov.b64 %0, {%1, %2};" : "=l"(dst) : "r"(__float_as_uint(w)), "r"(__float_as_uint(w)))
#define FMA2(acc, x, y) \
    asm("fma.rn.f32x2 %0, %1, %2, %3;" : "=l"(acc) : "l"(x), "l"(y), "l"(acc))
#define ADD2(dst, x, y) \
    asm("add.rn.f32x2 %0, %1, %2;" : "=l"(dst) : "l"(x), "l"(y))
#define UNPACK2(lo, hi, src) \
    asm("mov.b64 {%0, %1}, %2;" : "=r"(lo), "=r"(hi) : "l"(src))
#define LDS_V2U64(x, y, addr) \
    asm volatile("ld.shared.v2.u64 {%0, %1}, [%2];" : "=l"(x), "=l"(y) : "r"(addr))

__device__ __forceinline__ unsigned smem_u32(const void* p) {
    unsigned r;
    asm("{ .reg .u64 t; cvta.to.shared.u64 t, %1; cvt.u32.u64 %0, t; }" : "=r"(r) : "l"(p));
    return r;
}

template <int L>
__device__ __forceinline__ void batch_loop(
    int B, bool active, unsigned cur,
    const float* __restrict__ wr, float* op, long ostride)
{
    unsigned long long ww[L];
#pragma unroll
    for (int l = 0; l < L; ++l) {
        const float w = __ldg(wr + l);
        PACK_DUP(ww[l], w);
    }

#pragma unroll 2
    for (int b = 0; b < B; ++b) {
        unsigned long long aA = 0ull, aB = 0ull, cA = 0ull, cB = 0ull;
#pragma unroll
        for (int l = 0; l < L; ++l) {
            unsigned long long d01, d2p;
            LDS_V2U64(d01, d2p, cur + l * 16);
            if (l & 1) { FMA2(aB, ww[l], d01); FMA2(cB, ww[l], d2p); }
            else       { FMA2(aA, ww[l], d01); FMA2(cA, ww[l], d2p); }
        }
        unsigned long long a01, a2p;
        ADD2(a01, aA, aB);
        ADD2(a2p, cA, cB);
        if (active) {
            unsigned lo, hi, lo2, hi2;
            UNPACK2(lo, hi, a01);
            UNPACK2(lo2, hi2, a2p);
            op[0] = __uint_as_float(lo);
            op[1] = __uint_as_float(hi);
            op[2] = __uint_as_float(lo2);
        }
        op += ostride;
        cur += 224u;   // 56 floats per batch
    }
}

__global__ __launch_bounds__(256) void posmix_kernel(
    const float* __restrict__ pos_atm, const float* __restrict__ pos_amn,
    const float* __restrict__ W_amn,  const float* __restrict__ W_atm,
    const int* __restrict__ seq,
    int B, int nres, int atoms, float* __restrict__ out)
{
    const int totrows = g_totrows;
    const int row0 = blockIdx.x * 4;
    if (row0 >= totrows) return;

    __shared__ float sdif[4 * B_MAX * 56];   // 14336 B: (slot, b, l, 4)

    const int tid  = threadIdx.x;
    const int slot = tid >> 6;
    const int v    = tid & 63;
    const int row  = row0 + slot;
    const bool active = (row < totrows);
    const int rowc = active ? row : (totrows - 1);

    const int rm    = g_rowmap[rowc];          // uniform per warp
    const int i     = rm & 2047;
    const int m     = (rm >> 11) & 15;
    const int start = rm >> 15;
    const int t     = seq[i];                  // uniform per warp
    const int L     = c_res_len[t];
    const bool is_amn = (m == L);

    // --- compute diffs for this slot's residue, all batches, into smem ---
    if (v < 3 * L) {
        const int l = v / 3;
        const int d = v - 3 * l;
        const float* paP = pos_atm + (size_t)start * 3 + v;
        const float* pnP = pos_amn + (size_t)i * 3 + d;
        float* sd = sdif + slot * (B_MAX * 56) + l * 4 + d;
        const long astr = (long)atoms * 3;
        const long nstr = (long)nres * 3;
#pragma unroll 4
        for (int b = 0; b < B; ++b)
            sd[b * 56] = paP[b * astr] - pnP[b * nstr];
    }

    // --- output pointer ---
    const float* wr = is_amn
        ? (W_amn + ((size_t)t * DV + v) * LMAXC)
        : (W_atm + (((size_t)t * LMAXC + m) * DV + v) * LMAXC);

    size_t base; long ostride;
    if (is_amn) {
        base    = (size_t)B * atoms * (DV * 3) + ((size_t)i * DV + v) * 3;
        ostride = (long)nres * (DV * 3);
    } else {
        base    = ((size_t)(start + m) * DV + v) * 3;
        ostride = (long)atoms * (DV * 3);
    }
    float* op = out + base;

    __syncthreads();

    const unsigned cur = smem_u32(sdif) + (unsigned)(slot * (B_MAX * 56)) * 4u;

    switch (L) {
        case  3: batch_loop< 3>(B, active, cur, wr, op, ostride); break;
        case  4: batch_loop< 4>(B, active, cur, wr, op, ostride); break;
        case  5: batch_loop< 5>(B, active, cur, wr, op, ostride); break;
        case  6: batch_loop< 6>(B, active, cur, wr, op, ostride); break;
        case  7: batch_loop< 7>(B, active, cur, wr, op, ostride); break;
        case  8: batch_loop< 8>(B, active, cur, wr, op, ostride); break;
        case  9: batch_loop< 9>(B, active, cur, wr, op, ostride); break;
        case 10: batch_loop<10>(B, active, cur, wr, op, ostride); break;
        case 11: batch_loop<11>(B, active, cur, wr, op, ostride); break;
        default: batch_loop<13>(B, active, cur, wr, op, ostride); break;
    }
}

// ---------------------------------------------------------------------------
extern "C" void kernel_launch(void* const* d_in, const int* in_sizes, int n_in,
                              void* d_out, int out_size) {
    const float* pos_atm = (const float*)d_in[0];
    const float* pos_amn = (const float*)d_in[1];
    const float* W_amn   = (const float*)d_in[2];
    const float* W_atm   = (const float*)d_in[3];
    const int*   seq     = (const int*)d_in[4];

    const int nres  = in_sizes[4];
    const int B     = in_sizes[1] / (nres * 3);
    const int atoms = in_sizes[0] / (B * 3);

    setup_kernel<<<1, 1024>>>(seq, nres);
    const int nblocks = (nres * (LMAXC + 1) + 3) / 4;   // upper bound; early-exit
    posmix_kernel<<<nblocks, 256>>>(pos_atm, pos_amn, W_amn, W_atm, seq,
                                    B, nres, atoms, (float*)d_out);
}